// round 6
// baseline (speedup 1.0000x reference)
#include <cuda_runtime.h>
#include <cuda_bf16.h>
#include <cstdint>

#define NNODES 25000
#define NEDGES 400000
#define DIM    1024
#define MPAD   25088          // 196 * 128
#define KDUAL  2048
#define BK     32
#define NSTAGE (KDUAL / BK)   // 64
#define STAGE_BYTES 32768     // 4 tiles x 8KB
#define SMEMSZ (3 * STAGE_BYTES + 1024)

// ---------------- device scratch ---------------------------------------------
__device__ int   g_deg[NNODES];
__device__ float g_deginv[NNODES];
__device__ int   g_rowptr[NNODES + 1];
__device__ int   g_fill[NNODES];
__device__ int   g_col[NEDGES];
__device__ float g_h[(size_t)NNODES * DIM];
__device__ __align__(256) __nv_bfloat16 g_A0hi[(size_t)MPAD * KDUAL];
__device__ __align__(256) __nv_bfloat16 g_A0lo[(size_t)MPAD * KDUAL];
__device__ __align__(256) __nv_bfloat16 g_A1hi[(size_t)MPAD * KDUAL];
__device__ __align__(256) __nv_bfloat16 g_A1lo[(size_t)MPAD * KDUAL];
__device__ __align__(256) __nv_bfloat16 g_Bhi[(size_t)DIM * KDUAL];   // [N=1024][K=2048] (W^T)
__device__ __align__(256) __nv_bfloat16 g_Blo[(size_t)DIM * KDUAL];

// ---------------- helpers ------------------------------------------------------
__device__ __forceinline__ uint32_t smem_u32_of(const void* p) {
    uint32_t a;
    asm("{ .reg .u64 t; cvta.to.shared.u64 t, %1; cvt.u32.u64 %0, t; }" : "=r"(a) : "l"(p));
    return a;
}

__device__ __forceinline__ uint32_t sw128(uint32_t off) {
    return off ^ ((off >> 3) & 0x70);
}

__device__ __forceinline__ void cp_async16(uint32_t saddr, const void* g) {
    asm volatile("cp.async.cg.shared.global [%0], [%1], 16;" :: "r"(saddr), "l"(g));
}

__device__ __forceinline__ void ldsm_x4(uint32_t* r, uint32_t addr) {
    asm volatile("ldmatrix.sync.aligned.m8n8.x4.shared.b16 {%0,%1,%2,%3}, [%4];"
                 : "=r"(r[0]), "=r"(r[1]), "=r"(r[2]), "=r"(r[3]) : "r"(addr));
}

__device__ __forceinline__ void mma_bf16(float* d, const uint32_t* a, const uint32_t* b) {
    asm volatile(
        "mma.sync.aligned.m16n8k16.row.col.f32.bf16.bf16.f32 "
        "{%0,%1,%2,%3}, {%4,%5,%6,%7}, {%8,%9}, {%0,%1,%2,%3};"
        : "+f"(d[0]), "+f"(d[1]), "+f"(d[2]), "+f"(d[3])
        : "r"(a[0]), "r"(a[1]), "r"(a[2]), "r"(a[3]), "r"(b[0]), "r"(b[1]));
}

// ---------------- CSR build ---------------------------------------------------
__global__ void zero_deg_kernel() {
    int i = blockIdx.x * blockDim.x + threadIdx.x;
    if (i < NNODES) g_deg[i] = 0;
}

__global__ void count_deg_kernel(const int* __restrict__ edge_dst) {
    int e = blockIdx.x * blockDim.x + threadIdx.x;
    if (e < NEDGES) atomicAdd(&g_deg[edge_dst[e]], 1);
}

__global__ void build_rowptr_kernel() {
    __shared__ int sums[1024];
    const int tid = threadIdx.x;
    const int CHUNK = 25;
    const int start = tid * CHUNK;
    int s = 0;
    for (int i = 0; i < CHUNK; ++i) {
        int idx = start + i;
        if (idx < NNODES) s += g_deg[idx];
    }
    sums[tid] = s;
    __syncthreads();
    for (int off = 1; off < 1024; off <<= 1) {
        int add = 0;
        if (tid >= off) add = sums[tid - off];
        __syncthreads();
        sums[tid] += add;
        __syncthreads();
    }
    int prefix = (tid > 0) ? sums[tid - 1] : 0;
    for (int i = 0; i < CHUNK; ++i) {
        int idx = start + i;
        if (idx < NNODES) {
            g_rowptr[idx] = prefix;
            int d = g_deg[idx];
            prefix += d;
            g_deginv[idx] = 1.0f / fmaxf((float)d, 1.0f);
            g_fill[idx] = 0;
        }
    }
    if (tid == 1023) g_rowptr[NNODES] = sums[1023];
}

__global__ void fill_csr_kernel(const int* __restrict__ edge_src,
                                const int* __restrict__ edge_dst) {
    int e = blockIdx.x * blockDim.x + threadIdx.x;
    if (e < NEDGES) {
        int dst = edge_dst[e];
        int pos = g_rowptr[dst] + atomicAdd(&g_fill[dst], 1);
        g_col[pos] = edge_src[e];
    }
}

// ---------------- conversions --------------------------------------------------
__device__ __forceinline__ void split_store4(__nv_bfloat16* hi, __nv_bfloat16* lo,
                                             size_t off, float4 v) {
    __nv_bfloat16 hx = __float2bfloat16(v.x), hy = __float2bfloat16(v.y);
    __nv_bfloat16 hz = __float2bfloat16(v.z), hw = __float2bfloat16(v.w);
    __nv_bfloat162 h0; h0.x = hx; h0.y = hy;
    __nv_bfloat162 h1; h1.x = hz; h1.y = hw;
    __nv_bfloat162 l0, l1;
    l0.x = __float2bfloat16(v.x - __bfloat162float(hx));
    l0.y = __float2bfloat16(v.y - __bfloat162float(hy));
    l1.x = __float2bfloat16(v.z - __bfloat162float(hz));
    l1.y = __float2bfloat16(v.w - __bfloat162float(hw));
    *reinterpret_cast<__nv_bfloat162*>(hi + off)     = h0;
    *reinterpret_cast<__nv_bfloat162*>(hi + off + 2) = h1;
    *reinterpret_cast<__nv_bfloat162*>(lo + off)     = l0;
    *reinterpret_cast<__nv_bfloat162*>(lo + off + 2) = l1;
}

__device__ __forceinline__ void split_store2(__nv_bfloat16* hi, __nv_bfloat16* lo,
                                             size_t off, float a, float b) {
    __nv_bfloat16 ha = __float2bfloat16(a), hb = __float2bfloat16(b);
    __nv_bfloat162 h; h.x = ha; h.y = hb;
    __nv_bfloat162 l;
    l.x = __float2bfloat16(a - __bfloat162float(ha));
    l.y = __float2bfloat16(b - __bfloat162float(hb));
    *reinterpret_cast<__nv_bfloat162*>(hi + off) = h;
    *reinterpret_cast<__nv_bfloat162*>(lo + off) = l;
}

// zero pad rows [25000, 25088)
__global__ void zero_pad_kernel() {
    int row = NNODES + blockIdx.x;          // 88 blocks
    int t = threadIdx.x;                    // 256 threads, 16B each
    size_t off = (size_t)row * KDUAL + t * 8;
    uint4 z = make_uint4(0, 0, 0, 0);
    *reinterpret_cast<uint4*>(g_A0hi + off) = z;
    *reinterpret_cast<uint4*>(g_A0lo + off) = z;
    *reinterpret_cast<uint4*>(g_A1hi + off) = z;
    *reinterpret_cast<uint4*>(g_A1lo + off) = z;
}

__global__ __launch_bounds__(256) void convertX_kernel(const float* __restrict__ x) {
    int row = blockIdx.x, t = threadIdx.x;
    float4 v = ((const float4*)(x + (size_t)row * DIM))[t];
    split_store4(g_A0hi, g_A0lo, (size_t)row * KDUAL + t * 4, v);
}

// W[k][n] fp32 -> B^T[n][koff+k] bf16 hi/lo
__global__ void transposeW_kernel(const float* __restrict__ W, int koff) {
    __shared__ float tile[32][33];
    int tx = threadIdx.x, ty = threadIdx.y;       // (32, 8)
    int nb = blockIdx.x * 32, kb = blockIdx.y * 32;
    #pragma unroll
    for (int i = 0; i < 32; i += 8)
        tile[ty + i][tx] = W[(size_t)(kb + ty + i) * DIM + nb + tx];
    __syncthreads();
    #pragma unroll
    for (int i = 0; i < 32; i += 8) {
        float v = tile[tx][ty + i];
        __nv_bfloat16 h = __float2bfloat16(v);
        size_t off = (size_t)(nb + ty + i) * KDUAL + koff + kb + tx;
        g_Bhi[off] = h;
        g_Blo[off] = __float2bfloat16(v - __bfloat162float(h));
    }
}

// ---------------- mean aggregation -> bf16 splits into A cols [1024,2048) ------
__global__ __launch_bounds__(256)
void aggregate_split_kernel(const float* __restrict__ feat,
                            __nv_bfloat16* __restrict__ ahi,
                            __nv_bfloat16* __restrict__ alo) {
    const int node = blockIdx.x;
    const int tid  = threadIdx.x;
    const int beg = g_rowptr[node];
    const int end = g_rowptr[node + 1];
    float4 acc = make_float4(0.f, 0.f, 0.f, 0.f);
    for (int i = beg; i < end; ++i) {
        int src = g_col[i];
        float4 v = ((const float4*)(feat + (size_t)src * DIM))[tid];
        acc.x += v.x; acc.y += v.y; acc.z += v.z; acc.w += v.w;
    }
    float di = g_deginv[node];
    acc.x *= di; acc.y *= di; acc.z *= di; acc.w *= di;
    split_store4(ahi, alo, (size_t)node * KDUAL + DIM + tid * 4, acc);
}

// ---------------- mma.sync bf16 GEMM (3-product fp32-accurate split) ------------
// C[M,1024] = A@B^T + bias; A=[MPAD,2048] hi/lo, B^T=[1024,2048] hi/lo.
// 128x128 CTA tile, BK=32, 3-stage cp.async, 8 warps each 64x32.
__global__ __launch_bounds__(256)
void gemm_mma_kernel(const __nv_bfloat16* __restrict__ Ahi,
                     const __nv_bfloat16* __restrict__ Alo,
                     const float* __restrict__ bias,
                     float* __restrict__ C,
                     __nv_bfloat16* __restrict__ OutHi,
                     __nv_bfloat16* __restrict__ OutLo,
                     int M, int relu) {
    extern __shared__ __align__(1024) char smem_raw[];
    const uint32_t base = (smem_u32_of(smem_raw) + 1023u) & ~1023u;

    const int t = threadIdx.x;
    const int lane = t & 31;
    const int w = t >> 5;
    const int wm = w >> 2;            // 0..1 -> M offset wm*64
    const int wn = w & 3;             // 0..3 -> N offset wn*32
    const int m0 = blockIdx.y * 128;
    const int n0 = blockIdx.x * 128;

    const char* pAhi = (const char*)Ahi + (size_t)m0 * 4096;
    const char* pAlo = (const char*)Alo + (size_t)m0 * 4096;
    const char* pBhi = (const char*)g_Bhi + (size_t)n0 * 4096;
    const char* pBlo = (const char*)g_Blo + (size_t)n0 * 4096;

    float acc[4][4][4];
    #pragma unroll
    for (int i = 0; i < 4; ++i)
        #pragma unroll
        for (int j = 0; j < 4; ++j)
            #pragma unroll
            for (int r = 0; r < 4; ++r) acc[i][j][r] = 0.f;

    // ldmatrix lane->address components
    const int rowA = lane & 15;              // A: lanes 0-15 chunk kk*2, 16-31 chunk kk*2+1
    const int csA  = lane >> 4;
    const int rowB = (lane & 7) | ((lane & 16) >> 1);  // B: 0-7/16-23 rows, 8-15/24-31 chunk+1
    const int csB  = (lane >> 3) & 1;

    auto load_stage = [&](int s) {
        uint32_t sb = base + (s % 3) * STAGE_BYTES;
        size_t kb = (size_t)s * BK * 2;       // byte offset along K
        const char* srcs[4] = { pAhi + kb, pAlo + kb, pBhi + kb, pBlo + kb };
        #pragma unroll
        for (int tile = 0; tile < 4; ++tile) {
            uint32_t tb = sb + tile * 8192;
            const char* g = srcs[tile];
            #pragma unroll
            for (int i = 0; i < 2; ++i) {
                int chunk = t + i * 256;      // 512 chunks of 16B per tile
                int row = chunk >> 2;
                int c   = chunk & 3;
                cp_async16(tb + sw128((uint32_t)(row * 64 + c * 16)),
                           g + (size_t)row * 4096 + c * 16);
            }
        }
        asm volatile("cp.async.commit_group;" ::: "memory");
    };

    load_stage(0);
    load_stage(1);

    #pragma unroll 1
    for (int s = 0; s < NSTAGE; ++s) {
        if (s == NSTAGE - 1)
            asm volatile("cp.async.wait_group 0;" ::: "memory");
        else
            asm volatile("cp.async.wait_group 1;" ::: "memory");
        __syncthreads();
        if (s + 2 < NSTAGE) load_stage(s + 2);   // buffer (s+2)%3 free: compute(s-1) done

        uint32_t sb = base + (s % 3) * STAGE_BYTES;
        const uint32_t sAhi = sb, sAlo = sb + 8192, sBhi = sb + 16384, sBlo = sb + 24576;

        #pragma unroll
        for (int kk = 0; kk < 2; ++kk) {
            uint32_t ah[4][4], al[4][4], bh[4][2], bl[4][2];
            #pragma unroll
            for (int mf = 0; mf < 4; ++mf) {
                int row = wm * 64 + mf * 16 + rowA;
                uint32_t off = sw128((uint32_t)(row * 64 + (kk * 2 + csA) * 16));
                ldsm_x4(ah[mf], sAhi + off);
                ldsm_x4(al[mf], sAlo + off);
            }
            #pragma unroll
            for (int nh = 0; nh < 2; ++nh) {
                int row = wn * 32 + nh * 16 + rowB;
                uint32_t off = sw128((uint32_t)(row * 64 + (kk * 2 + csB) * 16));
                uint32_t r[4];
                ldsm_x4(r, sBhi + off);
                bh[nh * 2][0] = r[0]; bh[nh * 2][1] = r[1];
                bh[nh * 2 + 1][0] = r[2]; bh[nh * 2 + 1][1] = r[3];
                ldsm_x4(r, sBlo + off);
                bl[nh * 2][0] = r[0]; bl[nh * 2][1] = r[1];
                bl[nh * 2 + 1][0] = r[2]; bl[nh * 2 + 1][1] = r[3];
            }
            #pragma unroll
            for (int mf = 0; mf < 4; ++mf)
                #pragma unroll
                for (int nf = 0; nf < 4; ++nf) {
                    mma_bf16(acc[mf][nf], ah[mf], bh[nf]);   // hi*hi
                    mma_bf16(acc[mf][nf], al[mf], bh[nf]);   // lo*hi
                    mma_bf16(acc[mf][nf], ah[mf], bl[nf]);   // hi*lo
                }
        }
        __syncthreads();
    }

    // ---------------- epilogue ----------------
    const int r_in = lane >> 2;
    const int c_in = (lane & 3) * 2;
    #pragma unroll
    for (int mf = 0; mf < 4; ++mf) {
        int mA = m0 + wm * 64 + mf * 16 + r_in;
        int mB = mA + 8;
        #pragma unroll
        for (int nf = 0; nf < 4; ++nf) {
            int n = n0 + wn * 32 + nf * 8 + c_in;
            float bx = bias[n], by = bias[n + 1];
            float v0 = acc[mf][nf][0] + bx, v1 = acc[mf][nf][1] + by;
            float v2 = acc[mf][nf][2] + bx, v3 = acc[mf][nf][3] + by;
            if (relu) {
                v0 = fmaxf(v0, 0.f); v1 = fmaxf(v1, 0.f);
                v2 = fmaxf(v2, 0.f); v3 = fmaxf(v3, 0.f);
            }
            if (mA < M) {
                *(float2*)(C + (size_t)mA * DIM + n) = make_float2(v0, v1);
                if (OutHi) split_store2(OutHi, OutLo, (size_t)mA * KDUAL + n, v0, v1);
            }
            if (mB < M) {
                *(float2*)(C + (size_t)mB * DIM + n) = make_float2(v2, v3);
                if (OutHi) split_store2(OutHi, OutLo, (size_t)mB * KDUAL + n, v2, v3);
            }
        }
    }
}

// ---------------- launch --------------------------------------------------------
extern "C" void kernel_launch(void* const* d_in, const int* in_sizes, int n_in,
                              void* d_out, int out_size) {
    const float* x    = (const float*)d_in[0];
    const int*   esrc = (const int*)d_in[1];
    const int*   edst = (const int*)d_in[2];
    const float* Ws0  = (const float*)d_in[3];
    const float* Wn0  = (const float*)d_in[4];
    const float* b0   = (const float*)d_in[5];
    const float* Ws1  = (const float*)d_in[6];
    const float* Wn1  = (const float*)d_in[7];
    const float* b1   = (const float*)d_in[8];
    float* out = (float*)d_out;

    float *h_p;
    __nv_bfloat16 *a0h, *a0l, *a1h, *a1l;
    cudaGetSymbolAddress((void**)&h_p, g_h);
    cudaGetSymbolAddress((void**)&a0h, g_A0hi);
    cudaGetSymbolAddress((void**)&a0l, g_A0lo);
    cudaGetSymbolAddress((void**)&a1h, g_A1hi);
    cudaGetSymbolAddress((void**)&a1l, g_A1lo);

    cudaFuncSetAttribute(gemm_mma_kernel,
                         cudaFuncAttributeMaxDynamicSharedMemorySize, SMEMSZ);

    // CSR
    zero_deg_kernel<<<(NNODES + 255) / 256, 256>>>();
    count_deg_kernel<<<(NEDGES + 255) / 256, 256>>>(edst);
    build_rowptr_kernel<<<1, 1024>>>();
    fill_csr_kernel<<<(NEDGES + 255) / 256, 256>>>(esrc, edst);

    // conversions
    zero_pad_kernel<<<MPAD - NNODES, 256>>>();
    convertX_kernel<<<NNODES, 256>>>(x);
    dim3 tgrid(32, 32), tblk(32, 8);
    transposeW_kernel<<<tgrid, tblk>>>(Ws0, 0);
    transposeW_kernel<<<tgrid, tblk>>>(Wn0, DIM);

    dim3 ggrid(8, MPAD / 128);

    // layer 0: h = relu(x@Ws0 + mean(x)@Wn0 + b0); also emit bf16 split into A1
    aggregate_split_kernel<<<NNODES, 256>>>(x, a0h, a0l);
    gemm_mma_kernel<<<ggrid, 256, SMEMSZ>>>(a0h, a0l, b0, h_p, a1h, a1l, NNODES, 1);

    // layer 1
    transposeW_kernel<<<tgrid, tblk>>>(Ws1, 0);
    transposeW_kernel<<<tgrid, tblk>>>(Wn1, DIM);
    aggregate_split_kernel<<<NNODES, 256>>>(h_p, a1h, a1l);
    gemm_mma_kernel<<<ggrid, 256, SMEMSZ>>>(a1h, a1l, b1, out, nullptr, nullptr, NNODES, 0);
}

// round 7
// speedup vs baseline: 1.0005x; 1.0005x over previous
#include <cuda_runtime.h>
#include <cuda_bf16.h>
#include <cstdint>

#define NNODES 25000
#define NEDGES 400000
#define DIM    1024
#define MPAD   25088          // 196 * 128
#define KDUAL  2048
#define BK     32
#define NSTAGE (KDUAL / BK)   // 64
#define STAGE_BYTES 32768     // 4 tiles x 8KB
#define SMEMSZ (3 * STAGE_BYTES + 1024)

// ---------------- device scratch ---------------------------------------------
__device__ int   g_deg[NNODES];
__device__ float g_deginv[NNODES];
__device__ int   g_rowptr[NNODES + 1];
__device__ int   g_fill[NNODES];
__device__ int   g_col[NEDGES];
__device__ float g_h[(size_t)NNODES * DIM];
__device__ __align__(256) __nv_bfloat16 g_A0hi[(size_t)MPAD * KDUAL];
__device__ __align__(256) __nv_bfloat16 g_A0lo[(size_t)MPAD * KDUAL];
__device__ __align__(256) __nv_bfloat16 g_A1hi[(size_t)MPAD * KDUAL];
__device__ __align__(256) __nv_bfloat16 g_A1lo[(size_t)MPAD * KDUAL];
__device__ __align__(256) __nv_bfloat16 g_Bhi[(size_t)DIM * KDUAL];   // [N=1024][K=2048] (W^T)
__device__ __align__(256) __nv_bfloat16 g_Blo[(size_t)DIM * KDUAL];

// ---------------- helpers ------------------------------------------------------
__device__ __forceinline__ uint32_t smem_u32_of(const void* p) {
    uint32_t a;
    asm("{ .reg .u64 t; cvta.to.shared.u64 t, %1; cvt.u32.u64 %0, t; }" : "=r"(a) : "l"(p));
    return a;
}

__device__ __forceinline__ uint32_t sw128(uint32_t off) {
    return off ^ ((off >> 3) & 0x70);
}

__device__ __forceinline__ void cp_async16(uint32_t saddr, const void* g) {
    asm volatile("cp.async.cg.shared.global [%0], [%1], 16;" :: "r"(saddr), "l"(g));
}

__device__ __forceinline__ void ldsm_x4(uint32_t* r, uint32_t addr) {
    asm volatile("ldmatrix.sync.aligned.m8n8.x4.shared.b16 {%0,%1,%2,%3}, [%4];"
                 : "=r"(r[0]), "=r"(r[1]), "=r"(r[2]), "=r"(r[3]) : "r"(addr));
}

__device__ __forceinline__ void mma_bf16(float* d, const uint32_t* a, const uint32_t* b) {
    asm volatile(
        "mma.sync.aligned.m16n8k16.row.col.f32.bf16.bf16.f32 "
        "{%0,%1,%2,%3}, {%4,%5,%6,%7}, {%8,%9}, {%0,%1,%2,%3};"
        : "+f"(d[0]), "+f"(d[1]), "+f"(d[2]), "+f"(d[3])
        : "r"(a[0]), "r"(a[1]), "r"(a[2]), "r"(a[3]), "r"(b[0]), "r"(b[1]));
}

// ---------------- CSR build ---------------------------------------------------
__global__ void zero_deg_kernel() {
    int i = blockIdx.x * blockDim.x + threadIdx.x;
    if (i < NNODES) g_deg[i] = 0;
}

__global__ void count_deg_kernel(const int* __restrict__ edge_dst) {
    int e = blockIdx.x * blockDim.x + threadIdx.x;
    if (e < NEDGES) atomicAdd(&g_deg[edge_dst[e]], 1);
}

__global__ void build_rowptr_kernel() {
    __shared__ int sums[1024];
    const int tid = threadIdx.x;
    const int CHUNK = 25;
    const int start = tid * CHUNK;
    int s = 0;
    for (int i = 0; i < CHUNK; ++i) {
        int idx = start + i;
        if (idx < NNODES) s += g_deg[idx];
    }
    sums[tid] = s;
    __syncthreads();
    for (int off = 1; off < 1024; off <<= 1) {
        int add = 0;
        if (tid >= off) add = sums[tid - off];
        __syncthreads();
        sums[tid] += add;
        __syncthreads();
    }
    int prefix = (tid > 0) ? sums[tid - 1] : 0;
    for (int i = 0; i < CHUNK; ++i) {
        int idx = start + i;
        if (idx < NNODES) {
            g_rowptr[idx] = prefix;
            int d = g_deg[idx];
            prefix += d;
            g_deginv[idx] = 1.0f / fmaxf((float)d, 1.0f);
            g_fill[idx] = 0;
        }
    }
    if (tid == 1023) g_rowptr[NNODES] = sums[1023];
}

__global__ void fill_csr_kernel(const int* __restrict__ edge_src,
                                const int* __restrict__ edge_dst) {
    int e = blockIdx.x * blockDim.x + threadIdx.x;
    if (e < NEDGES) {
        int dst = edge_dst[e];
        int pos = g_rowptr[dst] + atomicAdd(&g_fill[dst], 1);
        g_col[pos] = edge_src[e];
    }
}

// ---------------- conversions --------------------------------------------------
__device__ __forceinline__ void split_store4(__nv_bfloat16* hi, __nv_bfloat16* lo,
                                             size_t off, float4 v) {
    __nv_bfloat16 hx = __float2bfloat16(v.x), hy = __float2bfloat16(v.y);
    __nv_bfloat16 hz = __float2bfloat16(v.z), hw = __float2bfloat16(v.w);
    __nv_bfloat162 h0; h0.x = hx; h0.y = hy;
    __nv_bfloat162 h1; h1.x = hz; h1.y = hw;
    __nv_bfloat162 l0, l1;
    l0.x = __float2bfloat16(v.x - __bfloat162float(hx));
    l0.y = __float2bfloat16(v.y - __bfloat162float(hy));
    l1.x = __float2bfloat16(v.z - __bfloat162float(hz));
    l1.y = __float2bfloat16(v.w - __bfloat162float(hw));
    *reinterpret_cast<__nv_bfloat162*>(hi + off)     = h0;
    *reinterpret_cast<__nv_bfloat162*>(hi + off + 2) = h1;
    *reinterpret_cast<__nv_bfloat162*>(lo + off)     = l0;
    *reinterpret_cast<__nv_bfloat162*>(lo + off + 2) = l1;
}

__device__ __forceinline__ void split_store2(__nv_bfloat16* hi, __nv_bfloat16* lo,
                                             size_t off, float a, float b) {
    __nv_bfloat16 ha = __float2bfloat16(a), hb = __float2bfloat16(b);
    __nv_bfloat162 h; h.x = ha; h.y = hb;
    __nv_bfloat162 l;
    l.x = __float2bfloat16(a - __bfloat162float(ha));
    l.y = __float2bfloat16(b - __bfloat162float(hb));
    *reinterpret_cast<__nv_bfloat162*>(hi + off) = h;
    *reinterpret_cast<__nv_bfloat162*>(lo + off) = l;
}

// zero pad rows [25000, 25088)
__global__ void zero_pad_kernel() {
    int row = NNODES + blockIdx.x;          // 88 blocks
    int t = threadIdx.x;                    // 256 threads, 16B each
    size_t off = (size_t)row * KDUAL + t * 8;
    uint4 z = make_uint4(0, 0, 0, 0);
    *reinterpret_cast<uint4*>(g_A0hi + off) = z;
    *reinterpret_cast<uint4*>(g_A0lo + off) = z;
    *reinterpret_cast<uint4*>(g_A1hi + off) = z;
    *reinterpret_cast<uint4*>(g_A1lo + off) = z;
}

__global__ __launch_bounds__(256) void convertX_kernel(const float* __restrict__ x) {
    int row = blockIdx.x, t = threadIdx.x;
    float4 v = ((const float4*)(x + (size_t)row * DIM))[t];
    split_store4(g_A0hi, g_A0lo, (size_t)row * KDUAL + t * 4, v);
}

// W[k][n] fp32 -> B^T[n][koff+k] bf16 hi/lo
__global__ void transposeW_kernel(const float* __restrict__ W, int koff) {
    __shared__ float tile[32][33];
    int tx = threadIdx.x, ty = threadIdx.y;       // (32, 8)
    int nb = blockIdx.x * 32, kb = blockIdx.y * 32;
    #pragma unroll
    for (int i = 0; i < 32; i += 8)
        tile[ty + i][tx] = W[(size_t)(kb + ty + i) * DIM + nb + tx];
    __syncthreads();
    #pragma unroll
    for (int i = 0; i < 32; i += 8) {
        float v = tile[tx][ty + i];
        __nv_bfloat16 h = __float2bfloat16(v);
        size_t off = (size_t)(nb + ty + i) * KDUAL + koff + kb + tx;
        g_Bhi[off] = h;
        g_Blo[off] = __float2bfloat16(v - __bfloat162float(h));
    }
}

// ---------------- mean aggregation -> bf16 splits into A cols [1024,2048) ------
__global__ __launch_bounds__(256)
void aggregate_split_kernel(const float* __restrict__ feat,
                            __nv_bfloat16* __restrict__ ahi,
                            __nv_bfloat16* __restrict__ alo) {
    const int node = blockIdx.x;
    const int tid  = threadIdx.x;
    const int beg = g_rowptr[node];
    const int end = g_rowptr[node + 1];
    float4 acc = make_float4(0.f, 0.f, 0.f, 0.f);
    for (int i = beg; i < end; ++i) {
        int src = g_col[i];
        float4 v = ((const float4*)(feat + (size_t)src * DIM))[tid];
        acc.x += v.x; acc.y += v.y; acc.z += v.z; acc.w += v.w;
    }
    float di = g_deginv[node];
    acc.x *= di; acc.y *= di; acc.z *= di; acc.w *= di;
    split_store4(ahi, alo, (size_t)node * KDUAL + DIM + tid * 4, acc);
}

// ---------------- mma.sync bf16 GEMM (3-product fp32-accurate split) ------------
// C[M,1024] = A@B^T + bias; A=[MPAD,2048] hi/lo, B^T=[1024,2048] hi/lo.
// 128x128 CTA tile, BK=32, 3-stage cp.async, 8 warps each 64x32.
__global__ __launch_bounds__(256)
void gemm_mma_kernel(const __nv_bfloat16* __restrict__ Ahi,
                     const __nv_bfloat16* __restrict__ Alo,
                     const float* __restrict__ bias,
                     float* __restrict__ C,
                     __nv_bfloat16* __restrict__ OutHi,
                     __nv_bfloat16* __restrict__ OutLo,
                     int M, int relu) {
    extern __shared__ __align__(1024) char smem_raw[];
    const uint32_t base = (smem_u32_of(smem_raw) + 1023u) & ~1023u;

    const int t = threadIdx.x;
    const int lane = t & 31;
    const int w = t >> 5;
    const int wm = w >> 2;            // 0..1 -> M offset wm*64
    const int wn = w & 3;             // 0..3 -> N offset wn*32
    const int m0 = blockIdx.y * 128;
    const int n0 = blockIdx.x * 128;

    const char* pAhi = (const char*)Ahi + (size_t)m0 * 4096;
    const char* pAlo = (const char*)Alo + (size_t)m0 * 4096;
    const char* pBhi = (const char*)g_Bhi + (size_t)n0 * 4096;
    const char* pBlo = (const char*)g_Blo + (size_t)n0 * 4096;

    float acc[4][4][4];
    #pragma unroll
    for (int i = 0; i < 4; ++i)
        #pragma unroll
        for (int j = 0; j < 4; ++j)
            #pragma unroll
            for (int r = 0; r < 4; ++r) acc[i][j][r] = 0.f;

    // ldmatrix lane->address components
    const int rowA = lane & 15;              // A: lanes 0-15 chunk kk*2, 16-31 chunk kk*2+1
    const int csA  = lane >> 4;
    const int rowB = (lane & 7) | ((lane & 16) >> 1);  // B: 0-7/16-23 rows, 8-15/24-31 chunk+1
    const int csB  = (lane >> 3) & 1;

    auto load_stage = [&](int s) {
        uint32_t sb = base + (s % 3) * STAGE_BYTES;
        size_t kb = (size_t)s * BK * 2;       // byte offset along K
        const char* srcs[4] = { pAhi + kb, pAlo + kb, pBhi + kb, pBlo + kb };
        #pragma unroll
        for (int tile = 0; tile < 4; ++tile) {
            uint32_t tb = sb + tile * 8192;
            const char* g = srcs[tile];
            #pragma unroll
            for (int i = 0; i < 2; ++i) {
                int chunk = t + i * 256;      // 512 chunks of 16B per tile
                int row = chunk >> 2;
                int c   = chunk & 3;
                cp_async16(tb + sw128((uint32_t)(row * 64 + c * 16)),
                           g + (size_t)row * 4096 + c * 16);
            }
        }
        asm volatile("cp.async.commit_group;" ::: "memory");
    };

    load_stage(0);
    load_stage(1);

    #pragma unroll 1
    for (int s = 0; s < NSTAGE; ++s) {
        if (s == NSTAGE - 1)
            asm volatile("cp.async.wait_group 0;" ::: "memory");
        else
            asm volatile("cp.async.wait_group 1;" ::: "memory");
        __syncthreads();
        if (s + 2 < NSTAGE) load_stage(s + 2);   // buffer (s+2)%3 free: compute(s-1) done

        uint32_t sb = base + (s % 3) * STAGE_BYTES;
        const uint32_t sAhi = sb, sAlo = sb + 8192, sBhi = sb + 16384, sBlo = sb + 24576;

        #pragma unroll
        for (int kk = 0; kk < 2; ++kk) {
            uint32_t ah[4][4], al[4][4], bh[4][2], bl[4][2];
            #pragma unroll
            for (int mf = 0; mf < 4; ++mf) {
                int row = wm * 64 + mf * 16 + rowA;
                uint32_t off = sw128((uint32_t)(row * 64 + (kk * 2 + csA) * 16));
                ldsm_x4(ah[mf], sAhi + off);
                ldsm_x4(al[mf], sAlo + off);
            }
            #pragma unroll
            for (int nh = 0; nh < 2; ++nh) {
                int row = wn * 32 + nh * 16 + rowB;
                uint32_t off = sw128((uint32_t)(row * 64 + (kk * 2 + csB) * 16));
                uint32_t r[4];
                ldsm_x4(r, sBhi + off);
                bh[nh * 2][0] = r[0]; bh[nh * 2][1] = r[1];
                bh[nh * 2 + 1][0] = r[2]; bh[nh * 2 + 1][1] = r[3];
                ldsm_x4(r, sBlo + off);
                bl[nh * 2][0] = r[0]; bl[nh * 2][1] = r[1];
                bl[nh * 2 + 1][0] = r[2]; bl[nh * 2 + 1][1] = r[3];
            }
            #pragma unroll
            for (int mf = 0; mf < 4; ++mf)
                #pragma unroll
                for (int nf = 0; nf < 4; ++nf) {
                    mma_bf16(acc[mf][nf], ah[mf], bh[nf]);   // hi*hi
                    mma_bf16(acc[mf][nf], al[mf], bh[nf]);   // lo*hi
                    mma_bf16(acc[mf][nf], ah[mf], bl[nf]);   // hi*lo
                }
        }
        __syncthreads();
    }

    // ---------------- epilogue ----------------
    const int r_in = lane >> 2;
    const int c_in = (lane & 3) * 2;
    #pragma unroll
    for (int mf = 0; mf < 4; ++mf) {
        int mA = m0 + wm * 64 + mf * 16 + r_in;
        int mB = mA + 8;
        #pragma unroll
        for (int nf = 0; nf < 4; ++nf) {
            int n = n0 + wn * 32 + nf * 8 + c_in;
            float bx = bias[n], by = bias[n + 1];
            float v0 = acc[mf][nf][0] + bx, v1 = acc[mf][nf][1] + by;
            float v2 = acc[mf][nf][2] + bx, v3 = acc[mf][nf][3] + by;
            if (relu) {
                v0 = fmaxf(v0, 0.f); v1 = fmaxf(v1, 0.f);
                v2 = fmaxf(v2, 0.f); v3 = fmaxf(v3, 0.f);
            }
            if (mA < M) {
                *(float2*)(C + (size_t)mA * DIM + n) = make_float2(v0, v1);
                if (OutHi) split_store2(OutHi, OutLo, (size_t)mA * KDUAL + n, v0, v1);
            }
            if (mB < M) {
                *(float2*)(C + (size_t)mB * DIM + n) = make_float2(v2, v3);
                if (OutHi) split_store2(OutHi, OutLo, (size_t)mB * KDUAL + n, v2, v3);
            }
        }
    }
}

// ---------------- launch --------------------------------------------------------
extern "C" void kernel_launch(void* const* d_in, const int* in_sizes, int n_in,
                              void* d_out, int out_size) {
    const float* x    = (const float*)d_in[0];
    const int*   esrc = (const int*)d_in[1];
    const int*   edst = (const int*)d_in[2];
    const float* Ws0  = (const float*)d_in[3];
    const float* Wn0  = (const float*)d_in[4];
    const float* b0   = (const float*)d_in[5];
    const float* Ws1  = (const float*)d_in[6];
    const float* Wn1  = (const float*)d_in[7];
    const float* b1   = (const float*)d_in[8];
    float* out = (float*)d_out;

    float *h_p;
    __nv_bfloat16 *a0h, *a0l, *a1h, *a1l;
    cudaGetSymbolAddress((void**)&h_p, g_h);
    cudaGetSymbolAddress((void**)&a0h, g_A0hi);
    cudaGetSymbolAddress((void**)&a0l, g_A0lo);
    cudaGetSymbolAddress((void**)&a1h, g_A1hi);
    cudaGetSymbolAddress((void**)&a1l, g_A1lo);

    cudaFuncSetAttribute(gemm_mma_kernel,
                         cudaFuncAttributeMaxDynamicSharedMemorySize, SMEMSZ);

    // CSR
    zero_deg_kernel<<<(NNODES + 255) / 256, 256>>>();
    count_deg_kernel<<<(NEDGES + 255) / 256, 256>>>(edst);
    build_rowptr_kernel<<<1, 1024>>>();
    fill_csr_kernel<<<(NEDGES + 255) / 256, 256>>>(esrc, edst);

    // conversions
    zero_pad_kernel<<<MPAD - NNODES, 256>>>();
    convertX_kernel<<<NNODES, 256>>>(x);
    dim3 tgrid(32, 32), tblk(32, 8);
    transposeW_kernel<<<tgrid, tblk>>>(Ws0, 0);
    transposeW_kernel<<<tgrid, tblk>>>(Wn0, DIM);

    dim3 ggrid(8, MPAD / 128);

    // layer 0: h = relu(x@Ws0 + mean(x)@Wn0 + b0); also emit bf16 split into A1
    aggregate_split_kernel<<<NNODES, 256>>>(x, a0h, a0l);
    gemm_mma_kernel<<<ggrid, 256, SMEMSZ>>>(a0h, a0l, b0, h_p, a1h, a1l, NNODES, 1);

    // layer 1
    transposeW_kernel<<<tgrid, tblk>>>(Ws1, 0);
    transposeW_kernel<<<tgrid, tblk>>>(Wn1, DIM);
    aggregate_split_kernel<<<NNODES, 256>>>(h_p, a1h, a1l);
    gemm_mma_kernel<<<ggrid, 256, SMEMSZ>>>(a1h, a1l, b1, out, nullptr, nullptr, NNODES, 0);
}

// round 8
// speedup vs baseline: 1.0017x; 1.0011x over previous
#include <cuda_runtime.h>
#include <cuda_bf16.h>
#include <cstdint>

#define NNODES 25000
#define NEDGES 400000
#define DIM    1024
#define MPAD   25088          // 196 * 128
#define KDUAL  2048
#define BK     32
#define NSTAGE (KDUAL / BK)   // 64
#define STAGE_BYTES 32768     // 4 tiles x 8KB
#define SMEMSZ (3 * STAGE_BYTES + 1024)

// ---------------- device scratch ---------------------------------------------
__device__ int   g_deg[NNODES];
__device__ float g_deginv[NNODES];
__device__ int   g_rowptr[NNODES + 1];
__device__ int   g_fill[NNODES];
__device__ int   g_col[NEDGES];
__device__ float g_h[(size_t)NNODES * DIM];
__device__ __align__(256) __nv_bfloat16 g_A0hi[(size_t)MPAD * KDUAL];
__device__ __align__(256) __nv_bfloat16 g_A0lo[(size_t)MPAD * KDUAL];
__device__ __align__(256) __nv_bfloat16 g_A1hi[(size_t)MPAD * KDUAL];
__device__ __align__(256) __nv_bfloat16 g_A1lo[(size_t)MPAD * KDUAL];
__device__ __align__(256) __nv_bfloat16 g_Bhi[(size_t)DIM * KDUAL];   // [N=1024][K=2048] (W^T)
__device__ __align__(256) __nv_bfloat16 g_Blo[(size_t)DIM * KDUAL];

// ---------------- helpers ------------------------------------------------------
__device__ __forceinline__ uint32_t smem_u32_of(const void* p) {
    uint32_t a;
    asm("{ .reg .u64 t; cvta.to.shared.u64 t, %1; cvt.u32.u64 %0, t; }" : "=r"(a) : "l"(p));
    return a;
}

__device__ __forceinline__ uint32_t sw128(uint32_t off) {
    return off ^ ((off >> 3) & 0x70);
}

__device__ __forceinline__ void cp_async16(uint32_t saddr, const void* g) {
    asm volatile("cp.async.cg.shared.global [%0], [%1], 16;" :: "r"(saddr), "l"(g));
}

__device__ __forceinline__ void ldsm_x4(uint32_t* r, uint32_t addr) {
    asm volatile("ldmatrix.sync.aligned.m8n8.x4.shared.b16 {%0,%1,%2,%3}, [%4];"
                 : "=r"(r[0]), "=r"(r[1]), "=r"(r[2]), "=r"(r[3]) : "r"(addr));
}

__device__ __forceinline__ void mma_bf16(float* d, const uint32_t* a, const uint32_t* b) {
    asm volatile(
        "mma.sync.aligned.m16n8k16.row.col.f32.bf16.bf16.f32 "
        "{%0,%1,%2,%3}, {%4,%5,%6,%7}, {%8,%9}, {%0,%1,%2,%3};"
        : "+f"(d[0]), "+f"(d[1]), "+f"(d[2]), "+f"(d[3])
        : "r"(a[0]), "r"(a[1]), "r"(a[2]), "r"(a[3]), "r"(b[0]), "r"(b[1]));
}

// ---------------- CSR build ---------------------------------------------------
__global__ void zero_deg_kernel() {
    int i = blockIdx.x * blockDim.x + threadIdx.x;
    if (i < NNODES) g_deg[i] = 0;
}

__global__ void count_deg_kernel(const int* __restrict__ edge_dst) {
    int e = blockIdx.x * blockDim.x + threadIdx.x;
    if (e < NEDGES) atomicAdd(&g_deg[edge_dst[e]], 1);
}

__global__ void build_rowptr_kernel() {
    __shared__ int sums[1024];
    const int tid = threadIdx.x;
    const int CHUNK = 25;
    const int start = tid * CHUNK;
    int s = 0;
    for (int i = 0; i < CHUNK; ++i) {
        int idx = start + i;
        if (idx < NNODES) s += g_deg[idx];
    }
    sums[tid] = s;
    __syncthreads();
    for (int off = 1; off < 1024; off <<= 1) {
        int add = 0;
        if (tid >= off) add = sums[tid - off];
        __syncthreads();
        sums[tid] += add;
        __syncthreads();
    }
    int prefix = (tid > 0) ? sums[tid - 1] : 0;
    for (int i = 0; i < CHUNK; ++i) {
        int idx = start + i;
        if (idx < NNODES) {
            g_rowptr[idx] = prefix;
            int d = g_deg[idx];
            prefix += d;
            g_deginv[idx] = 1.0f / fmaxf((float)d, 1.0f);
            g_fill[idx] = 0;
        }
    }
    if (tid == 1023) g_rowptr[NNODES] = sums[1023];
}

__global__ void fill_csr_kernel(const int* __restrict__ edge_src,
                                const int* __restrict__ edge_dst) {
    int e = blockIdx.x * blockDim.x + threadIdx.x;
    if (e < NEDGES) {
        int dst = edge_dst[e];
        int pos = g_rowptr[dst] + atomicAdd(&g_fill[dst], 1);
        g_col[pos] = edge_src[e];
    }
}

// ---------------- conversions --------------------------------------------------
__device__ __forceinline__ void split_store4(__nv_bfloat16* hi, __nv_bfloat16* lo,
                                             size_t off, float4 v) {
    __nv_bfloat16 hx = __float2bfloat16(v.x), hy = __float2bfloat16(v.y);
    __nv_bfloat16 hz = __float2bfloat16(v.z), hw = __float2bfloat16(v.w);
    __nv_bfloat162 h0; h0.x = hx; h0.y = hy;
    __nv_bfloat162 h1; h1.x = hz; h1.y = hw;
    __nv_bfloat162 l0, l1;
    l0.x = __float2bfloat16(v.x - __bfloat162float(hx));
    l0.y = __float2bfloat16(v.y - __bfloat162float(hy));
    l1.x = __float2bfloat16(v.z - __bfloat162float(hz));
    l1.y = __float2bfloat16(v.w - __bfloat162float(hw));
    *reinterpret_cast<__nv_bfloat162*>(hi + off)     = h0;
    *reinterpret_cast<__nv_bfloat162*>(hi + off + 2) = h1;
    *reinterpret_cast<__nv_bfloat162*>(lo + off)     = l0;
    *reinterpret_cast<__nv_bfloat162*>(lo + off + 2) = l1;
}

__device__ __forceinline__ void split_store2(__nv_bfloat16* hi, __nv_bfloat16* lo,
                                             size_t off, float a, float b) {
    __nv_bfloat16 ha = __float2bfloat16(a), hb = __float2bfloat16(b);
    __nv_bfloat162 h; h.x = ha; h.y = hb;
    __nv_bfloat162 l;
    l.x = __float2bfloat16(a - __bfloat162float(ha));
    l.y = __float2bfloat16(b - __bfloat162float(hb));
    *reinterpret_cast<__nv_bfloat162*>(hi + off) = h;
    *reinterpret_cast<__nv_bfloat162*>(lo + off) = l;
}

// zero pad rows [25000, 25088)
__global__ void zero_pad_kernel() {
    int row = NNODES + blockIdx.x;          // 88 blocks
    int t = threadIdx.x;                    // 256 threads, 16B each
    size_t off = (size_t)row * KDUAL + t * 8;
    uint4 z = make_uint4(0, 0, 0, 0);
    *reinterpret_cast<uint4*>(g_A0hi + off) = z;
    *reinterpret_cast<uint4*>(g_A0lo + off) = z;
    *reinterpret_cast<uint4*>(g_A1hi + off) = z;
    *reinterpret_cast<uint4*>(g_A1lo + off) = z;
}

__global__ __launch_bounds__(256) void convertX_kernel(const float* __restrict__ x) {
    int row = blockIdx.x, t = threadIdx.x;
    float4 v = ((const float4*)(x + (size_t)row * DIM))[t];
    split_store4(g_A0hi, g_A0lo, (size_t)row * KDUAL + t * 4, v);
}

// W[k][n] fp32 -> B^T[n][koff+k] bf16 hi/lo
__global__ void transposeW_kernel(const float* __restrict__ W, int koff) {
    __shared__ float tile[32][33];
    int tx = threadIdx.x, ty = threadIdx.y;       // (32, 8)
    int nb = blockIdx.x * 32, kb = blockIdx.y * 32;
    #pragma unroll
    for (int i = 0; i < 32; i += 8)
        tile[ty + i][tx] = W[(size_t)(kb + ty + i) * DIM + nb + tx];
    __syncthreads();
    #pragma unroll
    for (int i = 0; i < 32; i += 8) {
        float v = tile[tx][ty + i];
        __nv_bfloat16 h = __float2bfloat16(v);
        size_t off = (size_t)(nb + ty + i) * KDUAL + koff + kb + tx;
        g_Bhi[off] = h;
        g_Blo[off] = __float2bfloat16(v - __bfloat162float(h));
    }
}

// ---------------- mean aggregation -> bf16 splits into A cols [1024,2048) ------
__global__ __launch_bounds__(256)
void aggregate_split_kernel(const float* __restrict__ feat,
                            __nv_bfloat16* __restrict__ ahi,
                            __nv_bfloat16* __restrict__ alo) {
    const int node = blockIdx.x;
    const int tid  = threadIdx.x;
    const int beg = g_rowptr[node];
    const int end = g_rowptr[node + 1];
    float4 acc = make_float4(0.f, 0.f, 0.f, 0.f);
    for (int i = beg; i < end; ++i) {
        int src = g_col[i];
        float4 v = ((const float4*)(feat + (size_t)src * DIM))[tid];
        acc.x += v.x; acc.y += v.y; acc.z += v.z; acc.w += v.w;
    }
    float di = g_deginv[node];
    acc.x *= di; acc.y *= di; acc.z *= di; acc.w *= di;
    split_store4(ahi, alo, (size_t)node * KDUAL + DIM + tid * 4, acc);
}

// ---------------- mma.sync bf16 GEMM (3-product fp32-accurate split) ------------
// C[M,1024] = A@B^T + bias; A=[MPAD,2048] hi/lo, B^T=[1024,2048] hi/lo.
// 128x128 CTA tile, BK=32, 3-stage cp.async, 8 warps each 64x32.
__global__ __launch_bounds__(256)
void gemm_mma_kernel(const __nv_bfloat16* __restrict__ Ahi,
                     const __nv_bfloat16* __restrict__ Alo,
                     const float* __restrict__ bias,
                     float* __restrict__ C,
                     __nv_bfloat16* __restrict__ OutHi,
                     __nv_bfloat16* __restrict__ OutLo,
                     int M, int relu) {
    extern __shared__ __align__(1024) char smem_raw[];
    const uint32_t base = (smem_u32_of(smem_raw) + 1023u) & ~1023u;

    const int t = threadIdx.x;
    const int lane = t & 31;
    const int w = t >> 5;
    const int wm = w >> 2;            // 0..1 -> M offset wm*64
    const int wn = w & 3;             // 0..3 -> N offset wn*32
    const int m0 = blockIdx.y * 128;
    const int n0 = blockIdx.x * 128;

    const char* pAhi = (const char*)Ahi + (size_t)m0 * 4096;
    const char* pAlo = (const char*)Alo + (size_t)m0 * 4096;
    const char* pBhi = (const char*)g_Bhi + (size_t)n0 * 4096;
    const char* pBlo = (const char*)g_Blo + (size_t)n0 * 4096;

    float acc[4][4][4];
    #pragma unroll
    for (int i = 0; i < 4; ++i)
        #pragma unroll
        for (int j = 0; j < 4; ++j)
            #pragma unroll
            for (int r = 0; r < 4; ++r) acc[i][j][r] = 0.f;

    // ldmatrix lane->address components
    const int rowA = lane & 15;              // A: lanes 0-15 chunk kk*2, 16-31 chunk kk*2+1
    const int csA  = lane >> 4;
    const int rowB = (lane & 7) | ((lane & 16) >> 1);  // B: 0-7/16-23 rows, 8-15/24-31 chunk+1
    const int csB  = (lane >> 3) & 1;

    auto load_stage = [&](int s) {
        uint32_t sb = base + (s % 3) * STAGE_BYTES;
        size_t kb = (size_t)s * BK * 2;       // byte offset along K
        const char* srcs[4] = { pAhi + kb, pAlo + kb, pBhi + kb, pBlo + kb };
        #pragma unroll
        for (int tile = 0; tile < 4; ++tile) {
            uint32_t tb = sb + tile * 8192;
            const char* g = srcs[tile];
            #pragma unroll
            for (int i = 0; i < 2; ++i) {
                int chunk = t + i * 256;      // 512 chunks of 16B per tile
                int row = chunk >> 2;
                int c   = chunk & 3;
                cp_async16(tb + sw128((uint32_t)(row * 64 + c * 16)),
                           g + (size_t)row * 4096 + c * 16);
            }
        }
        asm volatile("cp.async.commit_group;" ::: "memory");
    };

    load_stage(0);
    load_stage(1);

    #pragma unroll 1
    for (int s = 0; s < NSTAGE; ++s) {
        if (s == NSTAGE - 1)
            asm volatile("cp.async.wait_group 0;" ::: "memory");
        else
            asm volatile("cp.async.wait_group 1;" ::: "memory");
        __syncthreads();
        if (s + 2 < NSTAGE) load_stage(s + 2);   // buffer (s+2)%3 free: compute(s-1) done

        uint32_t sb = base + (s % 3) * STAGE_BYTES;
        const uint32_t sAhi = sb, sAlo = sb + 8192, sBhi = sb + 16384, sBlo = sb + 24576;

        #pragma unroll
        for (int kk = 0; kk < 2; ++kk) {
            uint32_t ah[4][4], al[4][4], bh[4][2], bl[4][2];
            #pragma unroll
            for (int mf = 0; mf < 4; ++mf) {
                int row = wm * 64 + mf * 16 + rowA;
                uint32_t off = sw128((uint32_t)(row * 64 + (kk * 2 + csA) * 16));
                ldsm_x4(ah[mf], sAhi + off);
                ldsm_x4(al[mf], sAlo + off);
            }
            #pragma unroll
            for (int nh = 0; nh < 2; ++nh) {
                int row = wn * 32 + nh * 16 + rowB;
                uint32_t off = sw128((uint32_t)(row * 64 + (kk * 2 + csB) * 16));
                uint32_t r[4];
                ldsm_x4(r, sBhi + off);
                bh[nh * 2][0] = r[0]; bh[nh * 2][1] = r[1];
                bh[nh * 2 + 1][0] = r[2]; bh[nh * 2 + 1][1] = r[3];
                ldsm_x4(r, sBlo + off);
                bl[nh * 2][0] = r[0]; bl[nh * 2][1] = r[1];
                bl[nh * 2 + 1][0] = r[2]; bl[nh * 2 + 1][1] = r[3];
            }
            #pragma unroll
            for (int mf = 0; mf < 4; ++mf)
                #pragma unroll
                for (int nf = 0; nf < 4; ++nf) {
                    mma_bf16(acc[mf][nf], ah[mf], bh[nf]);   // hi*hi
                    mma_bf16(acc[mf][nf], al[mf], bh[nf]);   // lo*hi
                    mma_bf16(acc[mf][nf], ah[mf], bl[nf]);   // hi*lo
                }
        }
        __syncthreads();
    }

    // ---------------- epilogue ----------------
    const int r_in = lane >> 2;
    const int c_in = (lane & 3) * 2;
    #pragma unroll
    for (int mf = 0; mf < 4; ++mf) {
        int mA = m0 + wm * 64 + mf * 16 + r_in;
        int mB = mA + 8;
        #pragma unroll
        for (int nf = 0; nf < 4; ++nf) {
            int n = n0 + wn * 32 + nf * 8 + c_in;
            float bx = bias[n], by = bias[n + 1];
            float v0 = acc[mf][nf][0] + bx, v1 = acc[mf][nf][1] + by;
            float v2 = acc[mf][nf][2] + bx, v3 = acc[mf][nf][3] + by;
            if (relu) {
                v0 = fmaxf(v0, 0.f); v1 = fmaxf(v1, 0.f);
                v2 = fmaxf(v2, 0.f); v3 = fmaxf(v3, 0.f);
            }
            if (mA < M) {
                *(float2*)(C + (size_t)mA * DIM + n) = make_float2(v0, v1);
                if (OutHi) split_store2(OutHi, OutLo, (size_t)mA * KDUAL + n, v0, v1);
            }
            if (mB < M) {
                *(float2*)(C + (size_t)mB * DIM + n) = make_float2(v2, v3);
                if (OutHi) split_store2(OutHi, OutLo, (size_t)mB * KDUAL + n, v2, v3);
            }
        }
    }
}

// ---------------- launch --------------------------------------------------------
extern "C" void kernel_launch(void* const* d_in, const int* in_sizes, int n_in,
                              void* d_out, int out_size) {
    const float* x    = (const float*)d_in[0];
    const int*   esrc = (const int*)d_in[1];
    const int*   edst = (const int*)d_in[2];
    const float* Ws0  = (const float*)d_in[3];
    const float* Wn0  = (const float*)d_in[4];
    const float* b0   = (const float*)d_in[5];
    const float* Ws1  = (const float*)d_in[6];
    const float* Wn1  = (const float*)d_in[7];
    const float* b1   = (const float*)d_in[8];
    float* out = (float*)d_out;

    float *h_p;
    __nv_bfloat16 *a0h, *a0l, *a1h, *a1l;
    cudaGetSymbolAddress((void**)&h_p, g_h);
    cudaGetSymbolAddress((void**)&a0h, g_A0hi);
    cudaGetSymbolAddress((void**)&a0l, g_A0lo);
    cudaGetSymbolAddress((void**)&a1h, g_A1hi);
    cudaGetSymbolAddress((void**)&a1l, g_A1lo);

    cudaFuncSetAttribute(gemm_mma_kernel,
                         cudaFuncAttributeMaxDynamicSharedMemorySize, SMEMSZ);

    // CSR
    zero_deg_kernel<<<(NNODES + 255) / 256, 256>>>();
    count_deg_kernel<<<(NEDGES + 255) / 256, 256>>>(edst);
    build_rowptr_kernel<<<1, 1024>>>();
    fill_csr_kernel<<<(NEDGES + 255) / 256, 256>>>(esrc, edst);

    // conversions
    zero_pad_kernel<<<MPAD - NNODES, 256>>>();
    convertX_kernel<<<NNODES, 256>>>(x);
    dim3 tgrid(32, 32), tblk(32, 8);
    transposeW_kernel<<<tgrid, tblk>>>(Ws0, 0);
    transposeW_kernel<<<tgrid, tblk>>>(Wn0, DIM);

    dim3 ggrid(8, MPAD / 128);

    // layer 0: h = relu(x@Ws0 + mean(x)@Wn0 + b0); also emit bf16 split into A1
    aggregate_split_kernel<<<NNODES, 256>>>(x, a0h, a0l);
    gemm_mma_kernel<<<ggrid, 256, SMEMSZ>>>(a0h, a0l, b0, h_p, a1h, a1l, NNODES, 1);

    // layer 1
    transposeW_kernel<<<tgrid, tblk>>>(Ws1, 0);
    transposeW_kernel<<<tgrid, tblk>>>(Wn1, DIM);
    aggregate_split_kernel<<<NNODES, 256>>>(h_p, a1h, a1l);
    gemm_mma_kernel<<<ggrid, 256, SMEMSZ>>>(a1h, a1l, b1, out, nullptr, nullptr, NNODES, 0);
}